// round 4
// baseline (speedup 1.0000x reference)
#include <cuda_runtime.h>
#include <cuda_bf16.h>
#include <stdint.h>

// Per-block partial maxima (absmax grid is capped at 4096 blocks by the host).
__device__ float g_partial[4096];
// Final per-tier quantization params (slot 0 unused by quant path).
__device__ float g_scale[4];
__device__ float g_rcp[4];

// Column-mapped abs-max over (tw_i * ts_i) for tiers 1..3.
// Thread t owns float4 column t; scale lives in a register; rows strided
// across the tier's blocks. 4x unroll front-batches 4 independent LDG.128s.
// Every block writes its partial max unconditionally -> no reset needed.
__global__ void absmax3_kernel(const float4* __restrict__ w1,
                               const float4* __restrict__ w2,
                               const float4* __restrict__ w3,
                               const float4* __restrict__ s1,
                               const float4* __restrict__ s2,
                               const float4* __restrict__ s3,
                               int rows1, int rows2, int rows3,
                               int nb1, int nb2, int nb3, int dim4) {
    const int b = blockIdx.x;
    const float4* __restrict__ w;
    const float4* __restrict__ s;
    int rows, nb, bi;
    if (b < nb1)            { w = w1; s = s1; rows = rows1; nb = nb1; bi = b; }
    else if (b < nb1 + nb2) { w = w2; s = s2; rows = rows2; nb = nb2; bi = b - nb1; }
    else                    { w = w3; s = s3; rows = rows3; nb = nb3; bi = b - nb1 - nb2; }

    const int c = threadIdx.x;           // blockDim.x == dim4 (256)
    const float4 sc = s[c];

    float m = 0.f;
    int r = bi;
    const int stride = nb;
    for (; r + 3 * stride < rows; r += 4 * stride) {
        float4 a0 = w[(size_t)r * dim4 + c];
        float4 a1 = w[(size_t)(r + stride) * dim4 + c];
        float4 a2 = w[(size_t)(r + 2 * stride) * dim4 + c];
        float4 a3 = w[(size_t)(r + 3 * stride) * dim4 + c];
        float m0 = fmaxf(fmaxf(fabsf(a0.x * sc.x), fabsf(a0.y * sc.y)),
                         fmaxf(fabsf(a0.z * sc.z), fabsf(a0.w * sc.w)));
        float m1 = fmaxf(fmaxf(fabsf(a1.x * sc.x), fabsf(a1.y * sc.y)),
                         fmaxf(fabsf(a1.z * sc.z), fabsf(a1.w * sc.w)));
        float m2 = fmaxf(fmaxf(fabsf(a2.x * sc.x), fabsf(a2.y * sc.y)),
                         fmaxf(fabsf(a2.z * sc.z), fabsf(a2.w * sc.w)));
        float m3 = fmaxf(fmaxf(fabsf(a3.x * sc.x), fabsf(a3.y * sc.y)),
                         fmaxf(fabsf(a3.z * sc.z), fabsf(a3.w * sc.w)));
        m = fmaxf(m, fmaxf(fmaxf(m0, m1), fmaxf(m2, m3)));
    }
    for (; r < rows; r += stride) {
        float4 a = w[(size_t)r * dim4 + c];
        m = fmaxf(m, fmaxf(fmaxf(fabsf(a.x * sc.x), fabsf(a.y * sc.y)),
                           fmaxf(fabsf(a.z * sc.z), fabsf(a.w * sc.w))));
    }

    #pragma unroll
    for (int o = 16; o; o >>= 1)
        m = fmaxf(m, __shfl_xor_sync(0xFFFFFFFFu, m, o));
    __shared__ float sm[32];
    const int lane = threadIdx.x & 31, wid = threadIdx.x >> 5;
    if (lane == 0) sm[wid] = m;
    __syncthreads();
    const int nwarps = blockDim.x >> 5;
    if (wid == 0) {
        m = (lane < nwarps) ? sm[lane] : 0.f;
        #pragma unroll
        for (int o = 16; o; o >>= 1)
            m = fmaxf(m, __shfl_xor_sync(0xFFFFFFFFu, m, o));
        if (lane == 0) g_partial[b] = m;
    }
}

// One block: reduce each tier's partial range, emit scale and RN reciprocal.
__global__ void finalize_kernel(int nb1, int nb2, int nb3) {
    const int tid = threadIdx.x;
    const int lane = tid & 31, wid = tid >> 5;
    const int nwarps = blockDim.x >> 5;
    __shared__ float red[32];

    int start = 0;
    #pragma unroll
    for (int t = 1; t < 4; t++) {
        const int count = (t == 1) ? nb1 : (t == 2) ? nb2 : nb3;
        const float mv  = (t == 1) ? 127.f : (t == 2) ? 31.f : 7.f;
        float m = 0.f;
        for (int i = tid; i < count; i += blockDim.x)
            m = fmaxf(m, g_partial[start + i]);
        #pragma unroll
        for (int o = 16; o; o >>= 1)
            m = fmaxf(m, __shfl_xor_sync(0xFFFFFFFFu, m, o));
        if (lane == 0) red[wid] = m;
        __syncthreads();
        if (wid == 0) {
            m = (lane < nwarps) ? red[lane] : 0.f;
            #pragma unroll
            for (int o = 16; o; o >>= 1)
                m = fmaxf(m, __shfl_xor_sync(0xFFFFFFFFu, m, o));
            if (lane == 0) {
                float s = fmaxf(m, 1e-8f) / mv;
                g_scale[t] = s;
                g_rcp[t] = 1.0f / s;   // RN reciprocal -> Markstein seed
            }
        }
        __syncthreads();
        start += count;
    }
    if (tid == 0) { g_scale[0] = 1.f; g_rcp[0] = 1.f; }
}

// Correctly rounded x/s via Markstein 3-FMA (s, r=RN(1/s) precomputed; all
// values in normal range here), then fake-quant.
__device__ __forceinline__ float fq(float x, float s, float r, float mv) {
    float q0 = x * r;
    float e  = fmaf(-s, q0, x);
    float q  = fmaf(e, r, q0);
    return fminf(fmaxf(rintf(q), -mv), mv) * s;
}

// One block per token, one float4 per thread (blockDim == dim4).
// ids are int32 (JAX default int).
__global__ void gather_kernel(const int* __restrict__ ids,
                              const float4* __restrict__ tw0,
                              const float4* __restrict__ tw1,
                              const float4* __restrict__ tw2,
                              const float4* __restrict__ tw3,
                              const float4* __restrict__ ts0,
                              const float4* __restrict__ ts1,
                              const float4* __restrict__ ts2,
                              const float4* __restrict__ ts3,
                              float4* __restrict__ out,
                              int dim4, long b0, long b1, long b2, long vocab) {
    const int tok = blockIdx.x;
    long id = (long)__ldg(&ids[tok]);
    if (id < 0) id = 0;
    if (id >= vocab) id = vocab - 1;

    const float4* w; const float4* s;
    float mv = 0.f; int slot = 0;
    if (id < b0)      { w = tw0 + (size_t)id * dim4;        s = ts0; }
    else if (id < b1) { w = tw1 + (size_t)(id - b0) * dim4; s = ts1; mv = 127.f; slot = 1; }
    else if (id < b2) { w = tw2 + (size_t)(id - b1) * dim4; s = ts2; mv = 31.f;  slot = 2; }
    else              { w = tw3 + (size_t)(id - b2) * dim4; s = ts3; mv = 7.f;   slot = 3; }

    const int c = threadIdx.x;
    float4 v  = w[c];
    float4 sc = s[c];
    const float scale = g_scale[slot];
    const float rcp   = g_rcp[slot];

    v.x *= sc.x; v.y *= sc.y; v.z *= sc.z; v.w *= sc.w;
    if (slot > 0) {
        v.x = fq(v.x, scale, rcp, mv);
        v.y = fq(v.y, scale, rcp, mv);
        v.z = fq(v.z, scale, rcp, mv);
        v.w = fq(v.w, scale, rcp, mv);
    }
    out[(size_t)tok * dim4 + c] = v;
}

extern "C" void kernel_launch(void* const* d_in, const int* in_sizes, int n_in,
                              void* d_out, int out_size) {
    const int*   ids = (const int*)d_in[0];
    const float* tw0 = (const float*)d_in[1];
    const float* tw1 = (const float*)d_in[2];
    const float* tw2 = (const float*)d_in[3];
    const float* tw3 = (const float*)d_in[4];
    const float* ts0 = (const float*)d_in[5];
    const float* ts1 = (const float*)d_in[6];
    const float* ts2 = (const float*)d_in[7];
    const float* ts3 = (const float*)d_in[8];

    const int dim  = in_sizes[5];          // ts0 element count = embedding dim
    const int dim4 = dim / 4;
    const int ntok = in_sizes[0];

    const int r0 = in_sizes[1] / dim;      // tier row counts
    const int r1 = in_sizes[2] / dim;
    const int r2 = in_sizes[3] / dim;
    const int r3 = in_sizes[4] / dim;
    const long b0 = r0;                    // cumulative id boundaries
    const long b1 = b0 + r1;
    const long b2 = b1 + r2;
    const long vocab = b2 + r3;

    // Rows per block chosen so total blocks fit the partials array (4096).
    int rpb = 16;
    int nb1, nb2, nb3;
    for (;;) {
        nb1 = (r1 + rpb - 1) / rpb;
        nb2 = (r2 + rpb - 1) / rpb;
        nb3 = (r3 + rpb - 1) / rpb;
        if (nb1 + nb2 + nb3 <= 4096) break;
        rpb *= 2;
    }

    absmax3_kernel<<<nb1 + nb2 + nb3, dim4>>>(
        (const float4*)tw1, (const float4*)tw2, (const float4*)tw3,
        (const float4*)ts1, (const float4*)ts2, (const float4*)ts3,
        r1, r2, r3, nb1, nb2, nb3, dim4);

    finalize_kernel<<<1, 1024>>>(nb1, nb2, nb3);

    gather_kernel<<<ntok, dim4>>>(
        ids,
        (const float4*)tw0, (const float4*)tw1, (const float4*)tw2, (const float4*)tw3,
        (const float4*)ts0, (const float4*)ts1, (const float4*)ts2, (const float4*)ts3,
        (float4*)d_out, dim4, b0, b1, b2, vocab);
}

// round 5
// speedup vs baseline: 1.0792x; 1.0792x over previous
#include <cuda_runtime.h>
#include <cuda_bf16.h>
#include <stdint.h>

// Per-tier abs-max accumulators (slots 1..3). Non-negative float bits order
// like uints, so atomicMax on the uint view is an exact float max.
__device__ unsigned int g_absmax[4];

// Column-mapped abs-max over (tw_i * ts_i) for tiers 1..3.
// Thread t owns float4 column t; the scale value lives in a register; rows
// strided across the tier's blocks. 8x unroll front-batches 8 LDG.128s.
__global__ void absmax3_kernel(const float4* __restrict__ w1,
                               const float4* __restrict__ w2,
                               const float4* __restrict__ w3,
                               const float4* __restrict__ s1,
                               const float4* __restrict__ s2,
                               const float4* __restrict__ s3,
                               int rows1, int rows2, int rows3,
                               int nb1, int nb2, int nb3, int dim4) {
    const int b = blockIdx.x;
    const float4* __restrict__ w;
    const float4* __restrict__ s;
    int rows, nb, bi, slot;
    if (b < nb1)            { w = w1; s = s1; rows = rows1; nb = nb1; bi = b;             slot = 1; }
    else if (b < nb1 + nb2) { w = w2; s = s2; rows = rows2; nb = nb2; bi = b - nb1;       slot = 2; }
    else                    { w = w3; s = s3; rows = rows3; nb = nb3; bi = b - nb1 - nb2; slot = 3; }

    const int c = threadIdx.x;           // blockDim.x == dim4 (256)
    const float4 sc = s[c];

    float m = 0.f;
    int r = bi;
    const int stride = nb;
    for (; r + 7 * stride < rows; r += 8 * stride) {
        float4 a0 = w[(size_t)(r + 0 * stride) * dim4 + c];
        float4 a1 = w[(size_t)(r + 1 * stride) * dim4 + c];
        float4 a2 = w[(size_t)(r + 2 * stride) * dim4 + c];
        float4 a3 = w[(size_t)(r + 3 * stride) * dim4 + c];
        float4 a4 = w[(size_t)(r + 4 * stride) * dim4 + c];
        float4 a5 = w[(size_t)(r + 5 * stride) * dim4 + c];
        float4 a6 = w[(size_t)(r + 6 * stride) * dim4 + c];
        float4 a7 = w[(size_t)(r + 7 * stride) * dim4 + c];
        float m0 = fmaxf(fmaxf(fabsf(a0.x * sc.x), fabsf(a0.y * sc.y)),
                         fmaxf(fabsf(a0.z * sc.z), fabsf(a0.w * sc.w)));
        float m1 = fmaxf(fmaxf(fabsf(a1.x * sc.x), fabsf(a1.y * sc.y)),
                         fmaxf(fabsf(a1.z * sc.z), fabsf(a1.w * sc.w)));
        float m2 = fmaxf(fmaxf(fabsf(a2.x * sc.x), fabsf(a2.y * sc.y)),
                         fmaxf(fabsf(a2.z * sc.z), fabsf(a2.w * sc.w)));
        float m3 = fmaxf(fmaxf(fabsf(a3.x * sc.x), fabsf(a3.y * sc.y)),
                         fmaxf(fabsf(a3.z * sc.z), fabsf(a3.w * sc.w)));
        float m4 = fmaxf(fmaxf(fabsf(a4.x * sc.x), fabsf(a4.y * sc.y)),
                         fmaxf(fabsf(a4.z * sc.z), fabsf(a4.w * sc.w)));
        float m5 = fmaxf(fmaxf(fabsf(a5.x * sc.x), fabsf(a5.y * sc.y)),
                         fmaxf(fabsf(a5.z * sc.z), fabsf(a5.w * sc.w)));
        float m6 = fmaxf(fmaxf(fabsf(a6.x * sc.x), fabsf(a6.y * sc.y)),
                         fmaxf(fabsf(a6.z * sc.z), fabsf(a6.w * sc.w)));
        float m7 = fmaxf(fmaxf(fabsf(a7.x * sc.x), fabsf(a7.y * sc.y)),
                         fmaxf(fabsf(a7.z * sc.z), fabsf(a7.w * sc.w)));
        m = fmaxf(m, fmaxf(fmaxf(fmaxf(m0, m1), fmaxf(m2, m3)),
                           fmaxf(fmaxf(m4, m5), fmaxf(m6, m7))));
    }
    for (; r < rows; r += stride) {
        float4 a = w[(size_t)r * dim4 + c];
        m = fmaxf(m, fmaxf(fmaxf(fabsf(a.x * sc.x), fabsf(a.y * sc.y)),
                           fmaxf(fabsf(a.z * sc.z), fabsf(a.w * sc.w))));
    }

    #pragma unroll
    for (int o = 16; o; o >>= 1)
        m = fmaxf(m, __shfl_xor_sync(0xFFFFFFFFu, m, o));
    __shared__ float sm[32];
    const int lane = threadIdx.x & 31, wid = threadIdx.x >> 5;
    if (lane == 0) sm[wid] = m;
    __syncthreads();
    const int nwarps = blockDim.x >> 5;
    if (wid == 0) {
        m = (lane < nwarps) ? sm[lane] : 0.f;
        #pragma unroll
        for (int o = 16; o; o >>= 1)
            m = fmaxf(m, __shfl_xor_sync(0xFFFFFFFFu, m, o));
        if (lane == 0) atomicMax(&g_absmax[slot], __float_as_uint(m));
    }
}

// Correctly rounded x/s via Markstein 3-FMA (s and r = RN(1/s) precomputed;
// all values here are comfortably normal), then fake-quant.
__device__ __forceinline__ float fq(float x, float s, float r, float mv) {
    float q0 = x * r;
    float e  = fmaf(-s, q0, x);
    float q  = fmaf(e, r, q0);
    return fminf(fmaxf(rintf(q), -mv), mv) * s;
}

// Multi-token gather: each block handles TPB consecutive tokens with one
// float4 per thread per token (blockDim == dim4). Per-tier scale/rcp are
// computed once per block into smem. ids are int32.
__global__ void gather_kernel(const int* __restrict__ ids,
                              const float4* __restrict__ tw0,
                              const float4* __restrict__ tw1,
                              const float4* __restrict__ tw2,
                              const float4* __restrict__ tw3,
                              const float4* __restrict__ ts0,
                              const float4* __restrict__ ts1,
                              const float4* __restrict__ ts2,
                              const float4* __restrict__ ts3,
                              float4* __restrict__ out,
                              int dim4, long b0, long b1, long b2, long vocab,
                              int tpb, int ntok) {
    __shared__ float s_scale[4];
    __shared__ float s_rcp[4];
    if (threadIdx.x < 3) {
        const int t = threadIdx.x + 1;
        const float mv = (t == 1) ? 127.f : (t == 2) ? 31.f : 7.f;
        float sca = fmaxf(__uint_as_float(g_absmax[t]), 1e-8f) / mv;  // RN div
        s_scale[t] = sca;
        s_rcp[t] = __frcp_rn(sca);   // RN reciprocal -> exact Markstein seed
    }
    if (threadIdx.x == 3) { s_scale[0] = 1.f; s_rcp[0] = 1.f; }
    __syncthreads();

    const int c = threadIdx.x;
    const int t0 = blockIdx.x * tpb;

    for (int k = 0; k < tpb; k++) {
        const int tok = t0 + k;
        if (tok >= ntok) return;
        long id = (long)__ldg(&ids[tok]);
        if (id < 0) id = 0;
        if (id >= vocab) id = vocab - 1;

        const float4* w; const float4* s;
        float mv = 0.f; int slot = 0;
        if (id < b0)      { w = tw0 + (size_t)id * dim4;        s = ts0; }
        else if (id < b1) { w = tw1 + (size_t)(id - b0) * dim4; s = ts1; mv = 127.f; slot = 1; }
        else if (id < b2) { w = tw2 + (size_t)(id - b1) * dim4; s = ts2; mv = 31.f;  slot = 2; }
        else              { w = tw3 + (size_t)(id - b2) * dim4; s = ts3; mv = 7.f;   slot = 3; }

        float4 v  = w[c];
        float4 sc = s[c];
        const float scale = s_scale[slot];
        const float rcp   = s_rcp[slot];

        v.x *= sc.x; v.y *= sc.y; v.z *= sc.z; v.w *= sc.w;
        if (slot > 0) {
            v.x = fq(v.x, scale, rcp, mv);
            v.y = fq(v.y, scale, rcp, mv);
            v.z = fq(v.z, scale, rcp, mv);
            v.w = fq(v.w, scale, rcp, mv);
        }
        out[(size_t)tok * dim4 + c] = v;
    }
}

extern "C" void kernel_launch(void* const* d_in, const int* in_sizes, int n_in,
                              void* d_out, int out_size) {
    const int*   ids = (const int*)d_in[0];
    const float* tw0 = (const float*)d_in[1];
    const float* tw1 = (const float*)d_in[2];
    const float* tw2 = (const float*)d_in[3];
    const float* tw3 = (const float*)d_in[4];
    const float* ts0 = (const float*)d_in[5];
    const float* ts1 = (const float*)d_in[6];
    const float* ts2 = (const float*)d_in[7];
    const float* ts3 = (const float*)d_in[8];

    const int dim  = in_sizes[5];          // ts0 element count = embedding dim
    const int dim4 = dim / 4;
    const int ntok = in_sizes[0];

    const int r0 = in_sizes[1] / dim;      // tier row counts
    const int r1 = in_sizes[2] / dim;
    const int r2 = in_sizes[3] / dim;
    const int r3 = in_sizes[4] / dim;
    const long b0 = r0;                    // cumulative id boundaries
    const long b1 = b0 + r1;
    const long b2 = b1 + r2;
    const long vocab = b2 + r3;

    // ~16 rows per block per tier (tail handled by the strided loop).
    const int nb1 = (r1 + 15) / 16;
    const int nb2 = (r2 + 15) / 16;
    const int nb3 = (r3 + 15) / 16;

    void* absmax_addr = nullptr;
    cudaGetSymbolAddress(&absmax_addr, g_absmax);
    cudaMemsetAsync(absmax_addr, 0, 4 * sizeof(unsigned int));

    absmax3_kernel<<<nb1 + nb2 + nb3, dim4>>>(
        (const float4*)tw1, (const float4*)tw2, (const float4*)tw3,
        (const float4*)ts1, (const float4*)ts2, (const float4*)ts3,
        r1, r2, r3, nb1, nb2, nb3, dim4);

    const int tpb = 8;                     // tokens per gather block
    const int nblk = (ntok + tpb - 1) / tpb;
    gather_kernel<<<nblk, dim4>>>(
        ids,
        (const float4*)tw0, (const float4*)tw1, (const float4*)tw2, (const float4*)tw3,
        (const float4*)ts0, (const float4*)ts1, (const float4*)ts2, (const float4*)ts3,
        (float4*)d_out, dim4, b0, b1, b2, vocab, tpb, ntok);
}

// round 6
// speedup vs baseline: 1.1050x; 1.0239x over previous
#include <cuda_runtime.h>
#include <cuda_bf16.h>
#include <stdint.h>

// Per-tier abs-max accumulators (slots 1..3). Non-negative float bits order
// like uints, so atomicMax on the uint view is an exact float max.
__device__ unsigned int g_absmax[4];

// Column-mapped abs-max over (tw_i * ts_i) for tiers 1..3.
// Thread t owns float4 column t; the scale value lives in a register; rows
// strided across the tier's blocks. 8x unroll front-batches 8 LDG.128s.
__global__ void absmax3_kernel(const float4* __restrict__ w1,
                               const float4* __restrict__ w2,
                               const float4* __restrict__ w3,
                               const float4* __restrict__ s1,
                               const float4* __restrict__ s2,
                               const float4* __restrict__ s3,
                               int rows1, int rows2, int rows3,
                               int nb1, int nb2, int nb3, int dim4) {
    const int b = blockIdx.x;
    const float4* __restrict__ w;
    const float4* __restrict__ s;
    int rows, nb, bi, slot;
    if (b < nb1)            { w = w1; s = s1; rows = rows1; nb = nb1; bi = b;             slot = 1; }
    else if (b < nb1 + nb2) { w = w2; s = s2; rows = rows2; nb = nb2; bi = b - nb1;       slot = 2; }
    else                    { w = w3; s = s3; rows = rows3; nb = nb3; bi = b - nb1 - nb2; slot = 3; }

    const int c = threadIdx.x;           // blockDim.x == dim4 (256)
    const float4 sc = s[c];

    float m = 0.f;
    int r = bi;
    const int stride = nb;
    for (; r + 7 * stride < rows; r += 8 * stride) {
        float4 a0 = w[(size_t)(r + 0 * stride) * dim4 + c];
        float4 a1 = w[(size_t)(r + 1 * stride) * dim4 + c];
        float4 a2 = w[(size_t)(r + 2 * stride) * dim4 + c];
        float4 a3 = w[(size_t)(r + 3 * stride) * dim4 + c];
        float4 a4 = w[(size_t)(r + 4 * stride) * dim4 + c];
        float4 a5 = w[(size_t)(r + 5 * stride) * dim4 + c];
        float4 a6 = w[(size_t)(r + 6 * stride) * dim4 + c];
        float4 a7 = w[(size_t)(r + 7 * stride) * dim4 + c];
        float m0 = fmaxf(fmaxf(fabsf(a0.x * sc.x), fabsf(a0.y * sc.y)),
                         fmaxf(fabsf(a0.z * sc.z), fabsf(a0.w * sc.w)));
        float m1 = fmaxf(fmaxf(fabsf(a1.x * sc.x), fabsf(a1.y * sc.y)),
                         fmaxf(fabsf(a1.z * sc.z), fabsf(a1.w * sc.w)));
        float m2 = fmaxf(fmaxf(fabsf(a2.x * sc.x), fabsf(a2.y * sc.y)),
                         fmaxf(fabsf(a2.z * sc.z), fabsf(a2.w * sc.w)));
        float m3 = fmaxf(fmaxf(fabsf(a3.x * sc.x), fabsf(a3.y * sc.y)),
                         fmaxf(fabsf(a3.z * sc.z), fabsf(a3.w * sc.w)));
        float m4 = fmaxf(fmaxf(fabsf(a4.x * sc.x), fabsf(a4.y * sc.y)),
                         fmaxf(fabsf(a4.z * sc.z), fabsf(a4.w * sc.w)));
        float m5 = fmaxf(fmaxf(fabsf(a5.x * sc.x), fabsf(a5.y * sc.y)),
                         fmaxf(fabsf(a5.z * sc.z), fabsf(a5.w * sc.w)));
        float m6 = fmaxf(fmaxf(fabsf(a6.x * sc.x), fabsf(a6.y * sc.y)),
                         fmaxf(fabsf(a6.z * sc.z), fabsf(a6.w * sc.w)));
        float m7 = fmaxf(fmaxf(fabsf(a7.x * sc.x), fabsf(a7.y * sc.y)),
                         fmaxf(fabsf(a7.z * sc.z), fabsf(a7.w * sc.w)));
        m = fmaxf(m, fmaxf(fmaxf(fmaxf(m0, m1), fmaxf(m2, m3)),
                           fmaxf(fmaxf(m4, m5), fmaxf(m6, m7))));
    }
    for (; r < rows; r += stride) {
        float4 a = w[(size_t)r * dim4 + c];
        m = fmaxf(m, fmaxf(fmaxf(fabsf(a.x * sc.x), fabsf(a.y * sc.y)),
                           fmaxf(fabsf(a.z * sc.z), fabsf(a.w * sc.w))));
    }

    #pragma unroll
    for (int o = 16; o; o >>= 1)
        m = fmaxf(m, __shfl_xor_sync(0xFFFFFFFFu, m, o));
    __shared__ float sm[32];
    const int lane = threadIdx.x & 31, wid = threadIdx.x >> 5;
    if (lane == 0) sm[wid] = m;
    __syncthreads();
    const int nwarps = blockDim.x >> 5;
    if (wid == 0) {
        m = (lane < nwarps) ? sm[lane] : 0.f;
        #pragma unroll
        for (int o = 16; o; o >>= 1)
            m = fmaxf(m, __shfl_xor_sync(0xFFFFFFFFu, m, o));
        if (lane == 0) atomicMax(&g_absmax[slot], __float_as_uint(m));
    }
}

// Correctly rounded x/s via Markstein 3-FMA (s and r = RN(1/s) precomputed;
// all values here are comfortably normal), then fake-quant.
__device__ __forceinline__ float fq(float x, float s, float r, float mv) {
    float q0 = x * r;
    float e  = fmaf(-s, q0, x);
    float q  = fmaf(e, r, q0);
    return fminf(fmaxf(rintf(q), -mv), mv) * s;
}

#define TPB 8   // tokens per gather block

// Pipelined gather: 8 tokens per block, one float4 column per thread.
// Ids batched via int4 loads; all 8 row LDG.128s front-issued (MLP=8);
// the 4 tier scale vectors live in registers; per-tier quant params in smem.
__global__ __launch_bounds__(256)
void gather_kernel(const int* __restrict__ ids,
                   const float4* __restrict__ tw0,
                   const float4* __restrict__ tw1,
                   const float4* __restrict__ tw2,
                   const float4* __restrict__ tw3,
                   const float4* __restrict__ ts0,
                   const float4* __restrict__ ts1,
                   const float4* __restrict__ ts2,
                   const float4* __restrict__ ts3,
                   float4* __restrict__ out,
                   int dim4, long b0, long b1, long b2, long vocab,
                   int ntok) {
    __shared__ float s_scale[4];
    __shared__ float s_rcp[4];
    if (threadIdx.x < 3) {
        const int t = threadIdx.x + 1;
        const float mv = (t == 1) ? 127.f : (t == 2) ? 31.f : 7.f;
        float sca = fmaxf(__uint_as_float(g_absmax[t]), 1e-8f) / mv;  // RN div
        s_scale[t] = sca;
        s_rcp[t] = __frcp_rn(sca);   // RN reciprocal -> exact Markstein seed
    }
    if (threadIdx.x == 3) { s_scale[0] = 1.f; s_rcp[0] = 1.f; }

    const int c = threadIdx.x;
    // Register-cache the four scale-vector columns (4 independent loads).
    const float4 sc0 = ts0[c];
    const float4 sc1 = ts1[c];
    const float4 sc2 = ts2[c];
    const float4 sc3 = ts3[c];

    const int t0 = blockIdx.x * TPB;

    // Batch-load 8 consecutive ids (t0 is 8-aligned -> 16B-aligned int4s).
    const int4 ia = *reinterpret_cast<const int4*>(ids + t0);
    const int4 ib = *reinterpret_cast<const int4*>(ids + t0 + 4);
    int id8[TPB] = {ia.x, ia.y, ia.z, ia.w, ib.x, ib.y, ib.z, ib.w};

    const float4* wp[TPB];
    int slot8[TPB];
    #pragma unroll
    for (int k = 0; k < TPB; k++) {
        long id = (long)id8[k];
        if (id < 0) id = 0;
        if (id >= vocab) id = vocab - 1;
        const float4* w; int slot;
        if (id < b0)      { w = tw0 + (size_t)id * dim4;        slot = 0; }
        else if (id < b1) { w = tw1 + (size_t)(id - b0) * dim4; slot = 1; }
        else if (id < b2) { w = tw2 + (size_t)(id - b1) * dim4; slot = 2; }
        else              { w = tw3 + (size_t)(id - b2) * dim4; slot = 3; }
        wp[k] = w + c;
        slot8[k] = slot;
    }

    // Front-batch all 8 row loads.
    float4 v[TPB];
    #pragma unroll
    for (int k = 0; k < TPB; k++) v[k] = *wp[k];

    __syncthreads();   // s_scale/s_rcp ready (overlapped with the loads above)

    float4* o = out + (size_t)t0 * dim4 + c;
    #pragma unroll
    for (int k = 0; k < TPB; k++) {
        const int slot = slot8[k];
        float4 sc = sc0;
        if (slot == 1) sc = sc1;
        else if (slot == 2) sc = sc2;
        else if (slot == 3) sc = sc3;
        const float mv = (slot == 1) ? 127.f : (slot == 2) ? 31.f :
                         (slot == 3) ? 7.f : 0.f;
        const float scale = s_scale[slot];
        const float rcp   = s_rcp[slot];

        float4 x = v[k];
        x.x *= sc.x; x.y *= sc.y; x.z *= sc.z; x.w *= sc.w;
        if (slot > 0) {
            x.x = fq(x.x, scale, rcp, mv);
            x.y = fq(x.y, scale, rcp, mv);
            x.z = fq(x.z, scale, rcp, mv);
            x.w = fq(x.w, scale, rcp, mv);
        }
        *o = x;
        o += dim4;
    }
}

extern "C" void kernel_launch(void* const* d_in, const int* in_sizes, int n_in,
                              void* d_out, int out_size) {
    const int*   ids = (const int*)d_in[0];
    const float* tw0 = (const float*)d_in[1];
    const float* tw1 = (const float*)d_in[2];
    const float* tw2 = (const float*)d_in[3];
    const float* tw3 = (const float*)d_in[4];
    const float* ts0 = (const float*)d_in[5];
    const float* ts1 = (const float*)d_in[6];
    const float* ts2 = (const float*)d_in[7];
    const float* ts3 = (const float*)d_in[8];

    const int dim  = in_sizes[5];          // ts0 element count = embedding dim
    const int dim4 = dim / 4;
    const int ntok = in_sizes[0];

    const int r0 = in_sizes[1] / dim;      // tier row counts
    const int r1 = in_sizes[2] / dim;
    const int r2 = in_sizes[3] / dim;
    const int r3 = in_sizes[4] / dim;
    const long b0 = r0;                    // cumulative id boundaries
    const long b1 = b0 + r1;
    const long b2 = b1 + r2;
    const long vocab = b2 + r3;

    // ~16 rows per block per tier (tail handled by the strided loop).
    const int nb1 = (r1 + 15) / 16;
    const int nb2 = (r2 + 15) / 16;
    const int nb3 = (r3 + 15) / 16;

    void* absmax_addr = nullptr;
    cudaGetSymbolAddress(&absmax_addr, g_absmax);
    cudaMemsetAsync(absmax_addr, 0, 4 * sizeof(unsigned int));

    absmax3_kernel<<<nb1 + nb2 + nb3, dim4>>>(
        (const float4*)tw1, (const float4*)tw2, (const float4*)tw3,
        (const float4*)ts1, (const float4*)ts2, (const float4*)ts3,
        r1, r2, r3, nb1, nb2, nb3, dim4);

    const int nblk = (ntok + TPB - 1) / TPB;   // ntok = 16384, divisible by 8
    gather_kernel<<<nblk, dim4>>>(
        ids,
        (const float4*)tw0, (const float4*)tw1, (const float4*)tw2, (const float4*)tw3,
        (const float4*)ts0, (const float4*)ts1, (const float4*)ts2, (const float4*)ts3,
        (float4*)d_out, dim4, b0, b1, b2, vocab, ntok);
}

// round 7
// speedup vs baseline: 1.1056x; 1.0005x over previous
#include <cuda_runtime.h>
#include <cuda_bf16.h>
#include <stdint.h>

// Per-tier abs-max accumulators (slots 1..3). Non-negative float bits order
// like uints, so atomicMax on the uint view is an exact float max.
__device__ unsigned int g_absmax[4];

// Column-mapped abs-max over (tw_i * ts_i) for tiers 1..3.
// Thread t owns float4 column t; block bi owns a CONTIGUOUS 16-row chunk
// (32KB x 2 of contiguous DRAM per block). 8x unroll -> 8 LDG.128 in flight.
__global__ void absmax3_kernel(const float4* __restrict__ w1,
                               const float4* __restrict__ w2,
                               const float4* __restrict__ w3,
                               const float4* __restrict__ s1,
                               const float4* __restrict__ s2,
                               const float4* __restrict__ s3,
                               int rows1, int rows2, int rows3,
                               int nb1, int nb2, int nb3, int dim4, int rpb) {
    const int b = blockIdx.x;
    const float4* __restrict__ w;
    const float4* __restrict__ s;
    int rows, bi, slot;
    if (b < nb1)            { w = w1; s = s1; rows = rows1; bi = b;             slot = 1; }
    else if (b < nb1 + nb2) { w = w2; s = s2; rows = rows2; bi = b - nb1;       slot = 2; }
    else                    { w = w3; s = s3; rows = rows3; bi = b - nb1 - nb2; slot = 3; }

    const int c = threadIdx.x;           // blockDim.x == dim4 (256)
    const float4 sc = s[c];

    const int r0   = bi * rpb;
    const int rend = min(rows, r0 + rpb);

    float m = 0.f;
    int r = r0;
    for (; r + 7 < rend; r += 8) {
        float4 a0 = w[(size_t)(r + 0) * dim4 + c];
        float4 a1 = w[(size_t)(r + 1) * dim4 + c];
        float4 a2 = w[(size_t)(r + 2) * dim4 + c];
        float4 a3 = w[(size_t)(r + 3) * dim4 + c];
        float4 a4 = w[(size_t)(r + 4) * dim4 + c];
        float4 a5 = w[(size_t)(r + 5) * dim4 + c];
        float4 a6 = w[(size_t)(r + 6) * dim4 + c];
        float4 a7 = w[(size_t)(r + 7) * dim4 + c];
        float m0 = fmaxf(fmaxf(fabsf(a0.x * sc.x), fabsf(a0.y * sc.y)),
                         fmaxf(fabsf(a0.z * sc.z), fabsf(a0.w * sc.w)));
        float m1 = fmaxf(fmaxf(fabsf(a1.x * sc.x), fabsf(a1.y * sc.y)),
                         fmaxf(fabsf(a1.z * sc.z), fabsf(a1.w * sc.w)));
        float m2 = fmaxf(fmaxf(fabsf(a2.x * sc.x), fabsf(a2.y * sc.y)),
                         fmaxf(fabsf(a2.z * sc.z), fabsf(a2.w * sc.w)));
        float m3 = fmaxf(fmaxf(fabsf(a3.x * sc.x), fabsf(a3.y * sc.y)),
                         fmaxf(fabsf(a3.z * sc.z), fabsf(a3.w * sc.w)));
        float m4 = fmaxf(fmaxf(fabsf(a4.x * sc.x), fabsf(a4.y * sc.y)),
                         fmaxf(fabsf(a4.z * sc.z), fabsf(a4.w * sc.w)));
        float m5 = fmaxf(fmaxf(fabsf(a5.x * sc.x), fabsf(a5.y * sc.y)),
                         fmaxf(fabsf(a5.z * sc.z), fabsf(a5.w * sc.w)));
        float m6 = fmaxf(fmaxf(fabsf(a6.x * sc.x), fabsf(a6.y * sc.y)),
                         fmaxf(fabsf(a6.z * sc.z), fabsf(a6.w * sc.w)));
        float m7 = fmaxf(fmaxf(fabsf(a7.x * sc.x), fabsf(a7.y * sc.y)),
                         fmaxf(fabsf(a7.z * sc.z), fabsf(a7.w * sc.w)));
        m = fmaxf(m, fmaxf(fmaxf(fmaxf(m0, m1), fmaxf(m2, m3)),
                           fmaxf(fmaxf(m4, m5), fmaxf(m6, m7))));
    }
    for (; r < rend; r++) {
        float4 a = w[(size_t)r * dim4 + c];
        m = fmaxf(m, fmaxf(fmaxf(fabsf(a.x * sc.x), fabsf(a.y * sc.y)),
                           fmaxf(fabsf(a.z * sc.z), fabsf(a.w * sc.w))));
    }

    #pragma unroll
    for (int o = 16; o; o >>= 1)
        m = fmaxf(m, __shfl_xor_sync(0xFFFFFFFFu, m, o));
    __shared__ float sm[32];
    const int lane = threadIdx.x & 31, wid = threadIdx.x >> 5;
    if (lane == 0) sm[wid] = m;
    __syncthreads();
    const int nwarps = blockDim.x >> 5;
    if (wid == 0) {
        m = (lane < nwarps) ? sm[lane] : 0.f;
        #pragma unroll
        for (int o = 16; o; o >>= 1)
            m = fmaxf(m, __shfl_xor_sync(0xFFFFFFFFu, m, o));
        if (lane == 0) atomicMax(&g_absmax[slot], __float_as_uint(m));
    }
}

// Correctly rounded x/s via Markstein 3-FMA (s and r = RN(1/s) precomputed;
// all values here are comfortably normal), then fake-quant.
__device__ __forceinline__ float fq(float x, float s, float r, float mv) {
    float q0 = x * r;
    float e  = fmaf(-s, q0, x);
    float q  = fmaf(e, r, q0);
    return fminf(fmaxf(rintf(q), -mv), mv) * s;
}

// Warp-per-token gather: block = 8 warps = 8 tokens. All per-token state
// (id, pointer, slot, scale) is warp-uniform -> uniform registers. Lane l
// covers columns l+32*i: 8 front-batched LDG.128 over a contiguous 4KB row.
// ts scale vectors staged in smem; per-tier quant params in smem.
__global__ __launch_bounds__(256, 5)
void gather_kernel(const int* __restrict__ ids,
                   const float4* __restrict__ tw0,
                   const float4* __restrict__ tw1,
                   const float4* __restrict__ tw2,
                   const float4* __restrict__ tw3,
                   const float4* __restrict__ ts0,
                   const float4* __restrict__ ts1,
                   const float4* __restrict__ ts2,
                   const float4* __restrict__ ts3,
                   float4* __restrict__ out,
                   long b0, long b1, long b2, long vocab, int ntok) {
    __shared__ float4 s_ts[4][256];
    __shared__ float s_scale[4];
    __shared__ float s_rcp[4];

    const int c = threadIdx.x;
    // Stage the four scale vectors (4 independent LDG.128 + STS).
    s_ts[0][c] = ts0[c];
    s_ts[1][c] = ts1[c];
    s_ts[2][c] = ts2[c];
    s_ts[3][c] = ts3[c];
    if (c < 3) {
        const int t = c + 1;
        const float mvq = (t == 1) ? 127.f : (t == 2) ? 31.f : 7.f;
        float sca = fmaxf(__uint_as_float(g_absmax[t]), 1e-8f) / mvq;  // RN div
        s_scale[t] = sca;
        s_rcp[t] = __frcp_rn(sca);   // RN reciprocal -> exact Markstein seed
    }
    if (c == 3) { s_scale[0] = 1.f; s_rcp[0] = 1.f; }

    const int wid  = c >> 5;
    const int lane = c & 31;
    const int tok  = blockIdx.x * 8 + wid;

    // Warp-uniform token resolution.
    long id = 0;
    if (tok < ntok) id = (long)__ldg(&ids[tok]);
    if (id < 0) id = 0;
    if (id >= vocab) id = vocab - 1;

    const float4* w; int slot; float mv;
    if (id < b0)      { w = tw0 + (size_t)id * 256;        slot = 0; mv = 0.f; }
    else if (id < b1) { w = tw1 + (size_t)(id - b0) * 256; slot = 1; mv = 127.f; }
    else if (id < b2) { w = tw2 + (size_t)(id - b1) * 256; slot = 2; mv = 31.f; }
    else              { w = tw3 + (size_t)(id - b2) * 256; slot = 3; mv = 7.f; }

    // Front-batch the whole row: 8 LDG.128, contiguous 512B chunks.
    float4 v[8];
    #pragma unroll
    for (int i = 0; i < 8; i++) v[i] = w[lane + 32 * i];

    __syncthreads();   // smem staging done (overlapped with row loads)

    const float scale = s_scale[slot];
    const float rcp   = s_rcp[slot];
    float4* o = out + (size_t)tok * 256;

    if (tok >= ntok) return;

    #pragma unroll
    for (int i = 0; i < 8; i++) {
        const float4 sc = s_ts[slot][lane + 32 * i];   // LDS.128, conflict-free
        float4 x = v[i];
        x.x *= sc.x; x.y *= sc.y; x.z *= sc.z; x.w *= sc.w;
        if (slot > 0) {      // warp-uniform branch
            x.x = fq(x.x, scale, rcp, mv);
            x.y = fq(x.y, scale, rcp, mv);
            x.z = fq(x.z, scale, rcp, mv);
            x.w = fq(x.w, scale, rcp, mv);
        }
        o[lane + 32 * i] = x;
    }
}

extern "C" void kernel_launch(void* const* d_in, const int* in_sizes, int n_in,
                              void* d_out, int out_size) {
    const int*   ids = (const int*)d_in[0];
    const float* tw0 = (const float*)d_in[1];
    const float* tw1 = (const float*)d_in[2];
    const float* tw2 = (const float*)d_in[3];
    const float* tw3 = (const float*)d_in[4];
    const float* ts0 = (const float*)d_in[5];
    const float* ts1 = (const float*)d_in[6];
    const float* ts2 = (const float*)d_in[7];
    const float* ts3 = (const float*)d_in[8];

    const int dim  = in_sizes[5];          // ts0 element count = embedding dim
    const int dim4 = dim / 4;
    const int ntok = in_sizes[0];

    const int r0 = in_sizes[1] / dim;      // tier row counts
    const int r1 = in_sizes[2] / dim;
    const int r2 = in_sizes[3] / dim;
    const int r3 = in_sizes[4] / dim;
    const long b0 = r0;                    // cumulative id boundaries
    const long b1 = b0 + r1;
    const long b2 = b1 + r2;
    const long vocab = b2 + r3;

    const int rpb = 16;                    // contiguous rows per absmax block
    const int nb1 = (r1 + rpb - 1) / rpb;
    const int nb2 = (r2 + rpb - 1) / rpb;
    const int nb3 = (r3 + rpb - 1) / rpb;

    void* absmax_addr = nullptr;
    cudaGetSymbolAddress(&absmax_addr, g_absmax);
    cudaMemsetAsync(absmax_addr, 0, 4 * sizeof(unsigned int));

    absmax3_kernel<<<nb1 + nb2 + nb3, dim4>>>(
        (const float4*)tw1, (const float4*)tw2, (const float4*)tw3,
        (const float4*)ts1, (const float4*)ts2, (const float4*)ts3,
        r1, r2, r3, nb1, nb2, nb3, dim4, rpb);

    const int nblk = (ntok + 7) / 8;       // one warp per token, 8 per block
    gather_kernel<<<nblk, 256>>>(
        ids,
        (const float4*)tw0, (const float4*)tw1, (const float4*)tw2, (const float4*)tw3,
        (const float4*)ts0, (const float4*)ts1, (const float4*)ts2, (const float4*)ts3,
        (float4*)d_out, b0, b1, b2, vocab, ntok);
}

// round 8
// speedup vs baseline: 1.1449x; 1.0355x over previous
#include <cuda_runtime.h>
#include <cuda_bf16.h>
#include <stdint.h>

// Per-tier abs-max accumulators (slots 1..3). Non-negative float bits order
// like uints, so atomicMax on the uint view is an exact float max.
__device__ unsigned int g_absmax[4];

// Column-mapped abs-max over (tw_i * ts_i) for tiers 1..3 (strided rows —
// measured faster than contiguous chunks). 8x unroll -> 8 LDG.128 in flight.
__global__ void absmax3_kernel(const float4* __restrict__ w1,
                               const float4* __restrict__ w2,
                               const float4* __restrict__ w3,
                               const float4* __restrict__ s1,
                               const float4* __restrict__ s2,
                               const float4* __restrict__ s3,
                               int rows1, int rows2, int rows3,
                               int nb1, int nb2, int nb3, int dim4) {
    const int b = blockIdx.x;
    const float4* __restrict__ w;
    const float4* __restrict__ s;
    int rows, nb, bi, slot;
    if (b < nb1)            { w = w1; s = s1; rows = rows1; nb = nb1; bi = b;             slot = 1; }
    else if (b < nb1 + nb2) { w = w2; s = s2; rows = rows2; nb = nb2; bi = b - nb1;       slot = 2; }
    else                    { w = w3; s = s3; rows = rows3; nb = nb3; bi = b - nb1 - nb2; slot = 3; }

    const int c = threadIdx.x;           // blockDim.x == dim4 (256)
    const float4 sc = s[c];

    float m = 0.f;
    int r = bi;
    const int stride = nb;
    for (; r + 7 * stride < rows; r += 8 * stride) {
        float4 a0 = w[(size_t)(r + 0 * stride) * dim4 + c];
        float4 a1 = w[(size_t)(r + 1 * stride) * dim4 + c];
        float4 a2 = w[(size_t)(r + 2 * stride) * dim4 + c];
        float4 a3 = w[(size_t)(r + 3 * stride) * dim4 + c];
        float4 a4 = w[(size_t)(r + 4 * stride) * dim4 + c];
        float4 a5 = w[(size_t)(r + 5 * stride) * dim4 + c];
        float4 a6 = w[(size_t)(r + 6 * stride) * dim4 + c];
        float4 a7 = w[(size_t)(r + 7 * stride) * dim4 + c];
        float m0 = fmaxf(fmaxf(fabsf(a0.x * sc.x), fabsf(a0.y * sc.y)),
                         fmaxf(fabsf(a0.z * sc.z), fabsf(a0.w * sc.w)));
        float m1 = fmaxf(fmaxf(fabsf(a1.x * sc.x), fabsf(a1.y * sc.y)),
                         fmaxf(fabsf(a1.z * sc.z), fabsf(a1.w * sc.w)));
        float m2 = fmaxf(fmaxf(fabsf(a2.x * sc.x), fabsf(a2.y * sc.y)),
                         fmaxf(fabsf(a2.z * sc.z), fabsf(a2.w * sc.w)));
        float m3 = fmaxf(fmaxf(fabsf(a3.x * sc.x), fabsf(a3.y * sc.y)),
                         fmaxf(fabsf(a3.z * sc.z), fabsf(a3.w * sc.w)));
        float m4 = fmaxf(fmaxf(fabsf(a4.x * sc.x), fabsf(a4.y * sc.y)),
                         fmaxf(fabsf(a4.z * sc.z), fabsf(a4.w * sc.w)));
        float m5 = fmaxf(fmaxf(fabsf(a5.x * sc.x), fabsf(a5.y * sc.y)),
                         fmaxf(fabsf(a5.z * sc.z), fabsf(a5.w * sc.w)));
        float m6 = fmaxf(fmaxf(fabsf(a6.x * sc.x), fabsf(a6.y * sc.y)),
                         fmaxf(fabsf(a6.z * sc.z), fabsf(a6.w * sc.w)));
        float m7 = fmaxf(fmaxf(fabsf(a7.x * sc.x), fabsf(a7.y * sc.y)),
                         fmaxf(fabsf(a7.z * sc.z), fabsf(a7.w * sc.w)));
        m = fmaxf(m, fmaxf(fmaxf(fmaxf(m0, m1), fmaxf(m2, m3)),
                           fmaxf(fmaxf(m4, m5), fmaxf(m6, m7))));
    }
    for (; r < rows; r += stride) {
        float4 a = w[(size_t)r * dim4 + c];
        m = fmaxf(m, fmaxf(fmaxf(fabsf(a.x * sc.x), fabsf(a.y * sc.y)),
                           fmaxf(fabsf(a.z * sc.z), fabsf(a.w * sc.w))));
    }

    #pragma unroll
    for (int o = 16; o; o >>= 1)
        m = fmaxf(m, __shfl_xor_sync(0xFFFFFFFFu, m, o));
    __shared__ float sm[32];
    const int lane = threadIdx.x & 31, wid = threadIdx.x >> 5;
    if (lane == 0) sm[wid] = m;
    __syncthreads();
    const int nwarps = blockDim.x >> 5;
    if (wid == 0) {
        m = (lane < nwarps) ? sm[lane] : 0.f;
        #pragma unroll
        for (int o = 16; o; o >>= 1)
            m = fmaxf(m, __shfl_xor_sync(0xFFFFFFFFu, m, o));
        if (lane == 0) atomicMax(&g_absmax[slot], __float_as_uint(m));
    }
}

// Correctly rounded x/s via Markstein 3-FMA (s and r = RN(1/s) precomputed;
// all values here are comfortably normal), then fake-quant.
__device__ __forceinline__ float fq(float x, float s, float r, float mv) {
    float q0 = x * r;
    float e  = fmaf(-s, q0, x);
    float q  = fmaf(e, r, q0);
    return fminf(fmaxf(rintf(q), -mv), mv) * s;
}

__device__ __forceinline__ void cp_async16(void* smem_dst, const void* gmem_src) {
    uint32_t d = (uint32_t)__cvta_generic_to_shared(smem_dst);
    asm volatile("cp.async.cg.shared.global [%0], [%1], 16;" :: "r"(d), "l"(gmem_src));
}

// Warp-per-token gather with cp.async: block = 8 warps = 8 tokens. Rows and
// the 4 ts scale vectors are fetched global->smem via LDGSTS (bytes in flight
// live in the async pipe, not registers). Per-token state is warp-uniform.
__global__ __launch_bounds__(256)
void gather_kernel(const int* __restrict__ ids,
                   const float4* __restrict__ tw0,
                   const float4* __restrict__ tw1,
                   const float4* __restrict__ tw2,
                   const float4* __restrict__ tw3,
                   const float4* __restrict__ ts0,
                   const float4* __restrict__ ts1,
                   const float4* __restrict__ ts2,
                   const float4* __restrict__ ts3,
                   float4* __restrict__ out,
                   long b0, long b1, long b2, long vocab, int ntok) {
    __shared__ float4 s_row[8][256];   // 32 KB
    __shared__ float4 s_ts[4][256];    // 16 KB  (total = 48 KB static)

    const int c    = threadIdx.x;
    const int wid  = c >> 5;
    const int lane = c & 31;

    // Stage the four ts scale vectors.
    cp_async16(&s_ts[0][c], ts0 + c);
    cp_async16(&s_ts[1][c], ts1 + c);
    cp_async16(&s_ts[2][c], ts2 + c);
    cp_async16(&s_ts[3][c], ts3 + c);

    const int tok = blockIdx.x * 8 + wid;

    // Warp-uniform token resolution (clamped so OOB tok degrades safely).
    long id = 0;
    if (tok < ntok) id = (long)__ldg(&ids[tok]);
    if (id < 0) id = 0;
    if (id >= vocab) id = vocab - 1;

    const float4* w; int slot; float mv;
    if (id < b0)      { w = tw0 + (size_t)id * 256;        slot = 0; mv = 1.f; }
    else if (id < b1) { w = tw1 + (size_t)(id - b0) * 256; slot = 1; mv = 127.f; }
    else if (id < b2) { w = tw2 + (size_t)(id - b1) * 256; slot = 2; mv = 31.f; }
    else              { w = tw3 + (size_t)(id - b2) * 256; slot = 3; mv = 7.f; }

    // Async-fetch the whole 4KB row (8 x 16B per lane, contiguous 512B chunks).
    #pragma unroll
    for (int i = 0; i < 8; i++)
        cp_async16(&s_row[wid][lane + 32 * i], w + lane + 32 * i);

    asm volatile("cp.async.commit_group;" ::: "memory");

    // Per-warp quant params (uniform): one LDG.32 + RN div, overlapped with
    // the async copies.
    float scale = 1.f, rcp = 1.f;
    if (slot > 0) {
        scale = fmaxf(__uint_as_float(g_absmax[slot]), 1e-8f) / mv;  // RN div
        rcp   = __frcp_rn(scale);   // RN reciprocal -> exact Markstein seed
    }

    asm volatile("cp.async.wait_group 0;" ::: "memory");
    __syncthreads();   // s_ts written by all threads, read by all warps

    if (tok >= ntok) return;
    float4* o = out + (size_t)tok * 256;

    #pragma unroll
    for (int i = 0; i < 8; i++) {
        const float4 sc = s_ts[slot][lane + 32 * i];   // LDS.128, conflict-free
        float4 x = s_row[wid][lane + 32 * i];          // LDS.128, conflict-free
        x.x *= sc.x; x.y *= sc.y; x.z *= sc.z; x.w *= sc.w;
        if (slot > 0) {      // warp-uniform branch
            x.x = fq(x.x, scale, rcp, mv);
            x.y = fq(x.y, scale, rcp, mv);
            x.z = fq(x.z, scale, rcp, mv);
            x.w = fq(x.w, scale, rcp, mv);
        }
        o[lane + 32 * i] = x;
    }
}

extern "C" void kernel_launch(void* const* d_in, const int* in_sizes, int n_in,
                              void* d_out, int out_size) {
    const int*   ids = (const int*)d_in[0];
    const float* tw0 = (const float*)d_in[1];
    const float* tw1 = (const float*)d_in[2];
    const float* tw2 = (const float*)d_in[3];
    const float* tw3 = (const float*)d_in[4];
    const float* ts0 = (const float*)d_in[5];
    const float* ts1 = (const float*)d_in[6];
    const float* ts2 = (const float*)d_in[7];
    const float* ts3 = (const float*)d_in[8];

    const int dim  = in_sizes[5];          // ts0 element count = embedding dim
    const int dim4 = dim / 4;
    const int ntok = in_sizes[0];

    const int r0 = in_sizes[1] / dim;      // tier row counts
    const int r1 = in_sizes[2] / dim;
    const int r2 = in_sizes[3] / dim;
    const int r3 = in_sizes[4] / dim;
    const long b0 = r0;                    // cumulative id boundaries
    const long b1 = b0 + r1;
    const long b2 = b1 + r2;
    const long vocab = b2 + r3;

    // ~16 rows per block per tier, strided interleave (tail via loop).
    const int nb1 = (r1 + 15) / 16;
    const int nb2 = (r2 + 15) / 16;
    const int nb3 = (r3 + 15) / 16;

    void* absmax_addr = nullptr;
    cudaGetSymbolAddress(&absmax_addr, g_absmax);
    cudaMemsetAsync(absmax_addr, 0, 4 * sizeof(unsigned int));

    absmax3_kernel<<<nb1 + nb2 + nb3, dim4>>>(
        (const float4*)tw1, (const float4*)tw2, (const float4*)tw3,
        (const float4*)ts1, (const float4*)ts2, (const float4*)ts3,
        r1, r2, r3, nb1, nb2, nb3, dim4);

    const int nblk = (ntok + 7) / 8;       // one warp per token, 8 per block
    gather_kernel<<<nblk, 256>>>(
        ids,
        (const float4*)tw0, (const float4*)tw1, (const float4*)tw2, (const float4*)tw3,
        (const float4*)ts0, (const float4*)ts1, (const float4*)ts2, (const float4*)ts3,
        (float4*)d_out, b0, b1, b2, vocab, ntok);
}